// round 1
// baseline (speedup 1.0000x reference)
#include <cuda_runtime.h>
#include <cuda_bf16.h>

// Retrace loss:
//   c      = clip(tp/bp, 1e-10, 1)
//   a[k]   = rewards[k] + g*eQ[k+1] - g*c[k+1]*tQ[k+1]   (k = 1..1023)
//   b[k]   = g*c[k+1]
//   Q_ret[1023] = Q[1024];  Q_ret[j] = a[j+1] + b[j+1]*Q_ret[j+1]
//   out    = mean over (B,1024) of (Q[j] - Q_ret[j])^2
//
// One block (1024 threads) per row. Thread j owns timestep j and carries the
// affine transform T_j = (a[j+1], b[j+1]) (identity for j==1023). Suffix scan
// of affine composition gives Q_ret[j] = S_j.a + S_j.b * Q[1024].

#define GAMMA 0.99f
#define TLEN 1024
#define STRIDE 1025

__global__ void zero_out_kernel(float* out) {
    out[0] = 0.0f;
}

__global__ __launch_bounds__(1024, 2)
void retrace_kernel(const float* __restrict__ Q,
                    const float* __restrict__ eQ,
                    const float* __restrict__ tQ,
                    const float* __restrict__ rw,
                    const float* __restrict__ tp,
                    const float* __restrict__ bp,
                    float* __restrict__ out,
                    int B) {
    const int j    = threadIdx.x;        // 0..1023
    const int lane = j & 31;
    const int warp = j >> 5;
    const long base = (long)blockIdx.x * STRIDE;

    // ---- coalesced loads (each byte touched once across the grid) ----
    const float Qj    = Q[base + j];
    const float Qlast = __ldg(&Q[base + TLEN]);   // broadcast, one line

    float a, b;
    if (j < TLEN - 1) {
        const float r = rw[base + j + 1];
        const float e = eQ[base + j + 2];
        const float t = tQ[base + j + 2];
        float c = tp[base + j + 2] / bp[base + j + 2];
        c = fminf(fmaxf(c, 1e-10f), 1.0f);
        b = GAMMA * c;
        a = fmaf(GAMMA, e, r) - b * t;   // r + g*e - (g*c)*t
    } else {
        a = 0.0f;                        // identity transform for j == 1023
        b = 1.0f;
    }

    // ---- level 1: inclusive suffix scan within warp (Hillis-Steele) ----
    // compose(self, right): (A,B) <- (A + B*oA, B*oB)
    float A = a, Bv = b;
    #pragma unroll
    for (int d = 1; d < 32; d <<= 1) {
        float oA = __shfl_down_sync(0xffffffffu, A,  d);
        float oB = __shfl_down_sync(0xffffffffu, Bv, d);
        if (lane + d < 32) {
            A  = fmaf(Bv, oA, A);
            Bv = Bv * oB;
        }
    }

    // ---- level 2: scan of 32 warp aggregates by warp 0 ----
    __shared__ float sA[32], sB[32];
    __shared__ float eA[33], eB[33];
    if (lane == 0) { sA[warp] = A; sB[warp] = Bv; }   // lane 0 holds warp aggregate
    __syncthreads();
    if (warp == 0) {
        float wA = sA[lane], wB = sB[lane];
        #pragma unroll
        for (int d = 1; d < 32; d <<= 1) {
            float oA = __shfl_down_sync(0xffffffffu, wA, d);
            float oB = __shfl_down_sync(0xffffffffu, wB, d);
            if (lane + d < 32) {
                wA = fmaf(wB, oA, wA);
                wB = wB * oB;
            }
        }
        eA[lane] = wA; eB[lane] = wB;                 // inclusive suffix of warps
        if (lane == 0) { eA[32] = 0.0f; eB[32] = 1.0f; }
    }
    __syncthreads();

    // exclusive suffix (warps strictly to the right of mine)
    const float EA = eA[warp + 1];
    const float EB = eB[warp + 1];

    // total suffix transform for thread j, applied to Q[1024]
    const float Sa   = fmaf(Bv, EA, A);
    const float Sb   = Bv * EB;
    const float qret = fmaf(Sb, Qlast, Sa);

    float sq = (Qj - qret) * (Qj - qret);

    // ---- block reduction of squared error ----
    #pragma unroll
    for (int d = 16; d > 0; d >>= 1)
        sq += __shfl_xor_sync(0xffffffffu, sq, d);

    __shared__ float red[32];
    if (lane == 0) red[warp] = sq;
    __syncthreads();
    if (warp == 0) {
        float v = red[lane];
        #pragma unroll
        for (int d = 16; d > 0; d >>= 1)
            v += __shfl_xor_sync(0xffffffffu, v, d);
        if (lane == 0) {
            atomicAdd(out, v * (1.0f / ((float)B * (float)TLEN)));
        }
    }
}

extern "C" void kernel_launch(void* const* d_in, const int* in_sizes, int n_in,
                              void* d_out, int out_size) {
    const float* Q  = (const float*)d_in[0];
    const float* eQ = (const float*)d_in[1];
    const float* tQ = (const float*)d_in[2];
    const float* rw = (const float*)d_in[3];
    const float* tp = (const float*)d_in[4];
    const float* bp = (const float*)d_in[5];
    float* out = (float*)d_out;

    const int B = in_sizes[0] / STRIDE;   // 4096

    zero_out_kernel<<<1, 1>>>(out);
    retrace_kernel<<<B, 1024>>>(Q, eQ, tQ, rw, tp, bp, out, B);
}

// round 2
// speedup vs baseline: 1.2561x; 1.2561x over previous
#include <cuda_runtime.h>
#include <cuda_bf16.h>

// Retrace loss, suffix scan of affine transforms.
//   For j < 1023:  b[j] = g*clip(tp[j+2]/bp[j+2], eps, 1)
//                  a[j] = rw[j+1] + g*eQ[j+2] - b[j]*tQ[j+2]
//   j == 1023: identity (0,1)
//   Q_ret[j] = a[j] + b[j]*Q_ret[j+1], Q_ret beyond end = Q[1024]
//   out = mean (Q[j] - Q_ret[j])^2 over (4096, 1024)
//
// 256 threads/block, one row per block, 4 elements per thread, interleaved
// (j = t + 256*s) so every load is unit-stride coalesced. Hierarchy:
//   level 1: 4 independent 32-lane suffix scans (chunk = warp w of segment s)
//   level 2: single 32-lane scan of the 32 chunk aggregates (c = s*8 + w)

#define GAMMA 0.99f
#define TLEN 1024
#define STRIDE 1025

__global__ void zero_out_kernel(float* out) { out[0] = 0.0f; }

__global__ __launch_bounds__(256)
void retrace_kernel(const float* __restrict__ Q,
                    const float* __restrict__ eQ,
                    const float* __restrict__ tQ,
                    const float* __restrict__ rw,
                    const float* __restrict__ tp,
                    const float* __restrict__ bp,
                    float* __restrict__ out,
                    int B) {
    const int  t    = threadIdx.x;       // 0..255
    const int  lane = t & 31;
    const int  warp = t >> 5;            // 0..7
    const long base = (long)blockIdx.x * STRIDE;

    const float Qlast = __ldg(&Q[base + TLEN]);

    // ---- per-element transforms + Q values (all loads coalesced) ----
    float a[4], b[4], Qj[4];
    #pragma unroll
    for (int s = 0; s < 4; s++) {
        const int j = (s << 8) + t;
        Qj[s] = Q[base + j];
        if (j < TLEN - 1) {
            const float r  = rw[base + j + 1];
            const float e  = eQ[base + j + 2];
            const float tq = tQ[base + j + 2];
            float c = tp[base + j + 2] / bp[base + j + 2];
            c = fminf(fmaxf(c, 1e-10f), 1.0f);
            b[s] = GAMMA * c;
            a[s] = fmaf(GAMMA, e, r) - b[s] * tq;
        } else {                          // j == 1023: identity
            a[s] = 0.0f;
            b[s] = 1.0f;
        }
    }

    // ---- level 1: 4 independent warp suffix scans (ILP across s) ----
    // compose(self, right): (A,B) <- (A + B*oA, B*oB)
    #pragma unroll
    for (int d = 1; d < 32; d <<= 1) {
        #pragma unroll
        for (int s = 0; s < 4; s++) {
            float oA = __shfl_down_sync(0xffffffffu, a[s], d);
            float oB = __shfl_down_sync(0xffffffffu, b[s], d);
            if (lane + d < 32) {
                a[s] = fmaf(b[s], oA, a[s]);
                b[s] = b[s] * oB;
            }
        }
    }
    // a[s],b[s] now = inclusive suffix within chunk c = s*8 + warp
    // (chunk covers j = c*32 .. c*32+31; lane 0 holds the chunk aggregate)

    __shared__ float cA[32], cB[32];      // chunk aggregates
    __shared__ float iA[33], iB[33];      // inclusive chunk-suffix + identity
    if (lane == 0) {
        #pragma unroll
        for (int s = 0; s < 4; s++) {
            cA[(s << 3) + warp] = a[s];
            cB[(s << 3) + warp] = b[s];
        }
    }
    __syncthreads();

    // ---- level 2: one 32-lane scan over the 32 chunk aggregates ----
    if (warp == 0) {
        float wA = cA[lane], wB = cB[lane];
        #pragma unroll
        for (int d = 1; d < 32; d <<= 1) {
            float oA = __shfl_down_sync(0xffffffffu, wA, d);
            float oB = __shfl_down_sync(0xffffffffu, wB, d);
            if (lane + d < 32) {
                wA = fmaf(wB, oA, wA);
                wB = wB * oB;
            }
        }
        iA[lane] = wA; iB[lane] = wB;
        if (lane == 0) { iA[32] = 0.0f; iB[32] = 1.0f; }
    }
    __syncthreads();

    // ---- apply: Q_ret[j] = incl_lane( x_chunk ), accumulate squared error ----
    float sq = 0.0f;
    #pragma unroll
    for (int s = 0; s < 4; s++) {
        const int   c  = (s << 3) + warp;
        const float xc = fmaf(iB[c + 1], Qlast, iA[c + 1]);  // value at chunk right edge + 1
        const float qr = fmaf(b[s], xc, a[s]);
        const float d  = Qj[s] - qr;
        sq = fmaf(d, d, sq);
    }

    // ---- block reduction ----
    #pragma unroll
    for (int d = 16; d > 0; d >>= 1)
        sq += __shfl_xor_sync(0xffffffffu, sq, d);

    __shared__ float red[8];
    if (lane == 0) red[warp] = sq;
    __syncthreads();
    if (warp == 0) {
        float v = (lane < 8) ? red[lane] : 0.0f;
        #pragma unroll
        for (int d = 4; d > 0; d >>= 1)
            v += __shfl_xor_sync(0xffffffffu, v, d);
        if (lane == 0)
            atomicAdd(out, v * (1.0f / ((float)B * (float)TLEN)));
    }
}

extern "C" void kernel_launch(void* const* d_in, const int* in_sizes, int n_in,
                              void* d_out, int out_size) {
    const float* Q  = (const float*)d_in[0];
    const float* eQ = (const float*)d_in[1];
    const float* tQ = (const float*)d_in[2];
    const float* rw = (const float*)d_in[3];
    const float* tp = (const float*)d_in[4];
    const float* bp = (const float*)d_in[5];
    float* out = (float*)d_out;

    const int B = in_sizes[0] / STRIDE;   // 4096

    zero_out_kernel<<<1, 1>>>(out);
    retrace_kernel<<<B, 256>>>(Q, eQ, tQ, rw, tp, bp, out, B);
}